// round 10
// baseline (speedup 1.0000x reference)
#include <cuda_runtime.h>
#include <cuda_bf16.h>
#include <cstdint>
#include <math.h>

// KMeansClusteringLoss via warp-specialized bf16 HMMA pipeline (single kernel).
//   cost(l,c) = |mu_c|^2 - 2 <z_l, mu_c>,  d(l) = sqrt(max(|z_l|^2 + min_c cost, 0))
//   out = mean_l d(l)
//
// R10: 768 threads = 16 consumer warps (m16 x n256, ~73 regs -> fits 85-reg cap)
// + 8 producer warps. 4 consumer warps per SMSP give the tensor pipe phase
// diversity (LDSM/HMMA/fold phases of different warps overlap).

#define KDIM  128
#define CDIM  512
#define MT    128
#define NTHREADS 768       // warps 0-15 consumers, 16-23 producers
#define NQ    256          // centroids per consumer warp

#define STRIDE_B 272       // 128 bf16 (256B) + 16B pad -> conflict-free LDSM

// dynamic smem layout (bytes)
#define SM_MU    0                          // 512 x 272 = 139264
#define SM_Z0    139264                     // 128 x 272
#define SM_Z1    174080                     // 128 x 272
#define SM_M2    208896                     // 512 f32
#define SM_Z2_0  210944                     // 128 f32
#define SM_Z2_1  211456                     // 128 f32
#define SM_MH0   211968                     // 128 x 2 f32
#define SM_MH1   212992                     // 128 x 2 f32
#define SM_PT    214016                     // 2 ints
#define SMEM_BYTES 214048

__device__ float g_sum;            // zero-init at load; self-cleaned each run
__device__ unsigned int g_cnt;
__device__ unsigned int g_tile;

// ---------------- helpers ----------------
__device__ __forceinline__ uint32_t smem_u32(const void* p) {
    uint32_t a;
    asm("{ .reg .u64 t; cvta.to.shared.u64 t, %1; cvt.u32.u64 %0, t; }" : "=r"(a) : "l"(p));
    return a;
}
__device__ __forceinline__ void ldsm_x4(uint32_t& r0, uint32_t& r1, uint32_t& r2, uint32_t& r3,
                                        uint32_t addr) {
    asm volatile("ldmatrix.sync.aligned.m8n8.x4.shared.b16 {%0,%1,%2,%3}, [%4];"
                 : "=r"(r0), "=r"(r1), "=r"(r2), "=r"(r3) : "r"(addr));
}
__device__ __forceinline__ void mma_bf16(float* d, const uint32_t* a,
                                         uint32_t b0, uint32_t b1) {
    asm volatile(
        "mma.sync.aligned.m16n8k16.row.col.f32.bf16.bf16.f32 "
        "{%0,%1,%2,%3}, {%4,%5,%6,%7}, {%8,%9}, {%0,%1,%2,%3};"
        : "+f"(d[0]), "+f"(d[1]), "+f"(d[2]), "+f"(d[3])
        : "r"(a[0]), "r"(a[1]), "r"(a[2]), "r"(a[3]), "r"(b0), "r"(b1));
}
#define BAR_SYNC(id, cnt)   asm volatile("bar.sync %0, %1;"   :: "r"(id), "r"(cnt) : "memory")
#define BAR_ARRIVE(id, cnt) asm volatile("bar.arrive %0, %1;" :: "r"(id), "r"(cnt) : "memory")

// Fill a z tile: global fp32 -> bf16 packed smem.
__device__ __forceinline__ void fill_z(const float* __restrict__ z, int tile,
                                       char* smem, int zoff, int t, int nthr) {
    const size_t m0 = (size_t)tile * MT;
    for (int idx = t; idx < MT * 16; idx += nthr) {
        int row = idx >> 4, kc = idx & 15;
        const float4* p = reinterpret_cast<const float4*>(z + (m0 + row) * KDIM + kc * 8);
        float4 v0 = p[0], v1 = p[1];
        __nv_bfloat162 b0 = __floats2bfloat162_rn(v0.x, v0.y);
        __nv_bfloat162 b1 = __floats2bfloat162_rn(v0.z, v0.w);
        __nv_bfloat162 b2 = __floats2bfloat162_rn(v1.x, v1.y);
        __nv_bfloat162 b3 = __floats2bfloat162_rn(v1.z, v1.w);
        uint4 q;
        q.x = *reinterpret_cast<uint32_t*>(&b0);
        q.y = *reinterpret_cast<uint32_t*>(&b1);
        q.z = *reinterpret_cast<uint32_t*>(&b2);
        q.w = *reinterpret_cast<uint32_t*>(&b3);
        *reinterpret_cast<uint4*>(smem + zoff + row * STRIDE_B + kc * 16) = q;
    }
}

// |z|^2 second pass over a filled tile: 256 threads, 2 per row, 1 shfl.
__device__ __forceinline__ void z2_pass(const char* smem, int zoff, float* z2buf, int pt) {
    const int row = pt >> 1;
    const int half = pt & 1;
    float s = 0.0f;
    #pragma unroll
    for (int j = 0; j < 8; j++) {
        uint4 q = *reinterpret_cast<const uint4*>(smem + zoff + row * STRIDE_B
                                                  + half * 128 + j * 16);
        uint32_t u[4] = {q.x, q.y, q.z, q.w};
        #pragma unroll
        for (int e = 0; e < 4; e++) {
            float lo = __uint_as_float(u[e] << 16);
            float hi = __uint_as_float(u[e] & 0xffff0000u);
            s = fmaf(lo, lo, s);
            s = fmaf(hi, hi, s);
        }
    }
    s += __shfl_xor_sync(0xffffffffu, s, 1);     // pt parity == lane parity
    if (half == 0) z2buf[row] = s;
}

// ---------------- persistent warp-specialized kernel ----------------
__global__ void __launch_bounds__(NTHREADS, 1) km_main(
    const float* __restrict__ z, const float* __restrict__ mu,
    float* __restrict__ out, int L, int ntiles, int grid)
{
    extern __shared__ char smem[];
    const uint32_t sbase = smem_u32(smem);
    float* m2s = reinterpret_cast<float*>(smem + SM_M2);
    float* z2b[2] = { reinterpret_cast<float*>(smem + SM_Z2_0),
                      reinterpret_cast<float*>(smem + SM_Z2_1) };
    float* mhb[2] = { reinterpret_cast<float*>(smem + SM_MH0),
                      reinterpret_cast<float*>(smem + SM_MH1) };
    int* ptile = reinterpret_cast<int*>(smem + SM_PT);

    const int tid  = threadIdx.x;
    const int wid  = tid >> 5;
    const int lane = tid & 31;

    // ---- prologue: steal tile 0; mu fp32->bf16 into smem; m2; fill+z2 buf0 ----
    if (tid == 0) ptile[0] = (int)atomicAdd(&g_tile, 1u);

    for (int idx = tid; idx < CDIM * 16; idx += NTHREADS) {   // 16B chunks (bf16 out)
        int row = idx >> 4, kc = idx & 15;
        const float4* p = reinterpret_cast<const float4*>(mu + row * KDIM + kc * 8);
        float4 v0 = p[0], v1 = p[1];
        __nv_bfloat162 b0 = __floats2bfloat162_rn(v0.x, v0.y);
        __nv_bfloat162 b1 = __floats2bfloat162_rn(v0.z, v0.w);
        __nv_bfloat162 b2 = __floats2bfloat162_rn(v1.x, v1.y);
        __nv_bfloat162 b3 = __floats2bfloat162_rn(v1.z, v1.w);
        uint4 q;
        q.x = *reinterpret_cast<uint32_t*>(&b0);
        q.y = *reinterpret_cast<uint32_t*>(&b1);
        q.z = *reinterpret_cast<uint32_t*>(&b2);
        q.w = *reinterpret_cast<uint32_t*>(&b3);
        *reinterpret_cast<uint4*>(smem + SM_MU + row * STRIDE_B + kc * 16) = q;
    }
    __syncthreads();

    // m2 per centroid from the bf16 values (thread t -> centroid t)
    if (tid < CDIM) {
        float s = 0.0f;
        #pragma unroll
        for (int j = 0; j < 16; j++) {
            uint4 q = *reinterpret_cast<const uint4*>(smem + SM_MU + tid * STRIDE_B + j * 16);
            uint32_t u[4] = {q.x, q.y, q.z, q.w};
            #pragma unroll
            for (int e = 0; e < 4; e++) {
                float lo = __uint_as_float(u[e] << 16);
                float hi = __uint_as_float(u[e] & 0xffff0000u);
                s = fmaf(lo, lo, s);
                s = fmaf(hi, hi, s);
            }
        }
        m2s[tid] = s;
    }

    fill_z(z, ptile[0], smem, SM_Z0, tid, NTHREADS);
    __syncthreads();
    if (tid < 256) z2_pass(smem, SM_Z0, z2b[0], tid);
    __syncthreads();

    if (wid >= 16) {
        // ================= PRODUCER (warps 16-23) =================
        const int ptid = tid - 512;          // 0..255
        for (int i = 1;; i++) {
            const int p = i & 1;
            if (i >= 2) BAR_SYNC(3 + p, NTHREADS);            // wait buffer empty
            if (ptid == 0) {
                int t = (int)atomicAdd(&g_tile, 1u);
                ptile[p] = (t < ntiles) ? t : -1;
            }
            BAR_SYNC(6, 256);                                  // ptile visible
            const int t = ptile[p];
            if (t >= 0) {
                const int zoff = p ? SM_Z1 : SM_Z0;
                fill_z(z, t, smem, zoff, ptid, 256);
                BAR_SYNC(6, 256);                              // drain STS before z2 reads
                z2_pass(smem, zoff, z2b[p], ptid);
            }
            __threadfence_block();
            BAR_ARRIVE(1 + p, NTHREADS);                       // signal full
            if (t < 0) break;
        }
    } else {
        // ================= CONSUMER (warps 0-15) =================
        const int tg   = lane & 3;
        const int g    = lane >> 2;
        const int rw   = wid & 7;           // row-group (m16)
        const int nh   = wid >> 3;          // centroid half (0/1)
        const int r0   = rw * 16;
        const int nbase = nh * NQ;

        const uint32_t bb = sbase + SM_MU
                          + (lane & 7) * STRIDE_B
                          + (((lane >> 3) & 1) ? 16u : 0u)
                          + (lane >> 4) * 8 * STRIDE_B
                          + nbase * STRIDE_B;

        for (int i = 0;; i++) {
            const int p = i & 1;
            if (i >= 1) BAR_SYNC(1 + p, NTHREADS);             // wait buffer full
            const int t = ptile[p];
            if (t < 0) break;
            const uint32_t zb = sbase + (p ? SM_Z1 : SM_Z0);
            float* mhp = mhb[p];

            // ---- A fragments: m16 x K128 register-resident (32 regs) ----
            uint32_t A[8][4];
            {
                const uint32_t ab = zb + (lane & 15) * STRIDE_B
                                  + ((lane & 16) ? 16u : 0u) + r0 * STRIDE_B;
                #pragma unroll
                for (int kk = 0; kk < 8; kk++)
                    ldsm_x4(A[kk][0], A[kk][1], A[kk][2], A[kk][3], ab + kk * 32);
            }

            // ---- 256 centroids: 16 iters of n16, 2 chains ----
            float mn[2] = {INFINITY, INFINITY};
            #pragma unroll 1
            for (int nt = 0; nt < NQ / 16; nt++) {
                float acc[2][4] = {};
                const uint32_t ba = bb + nt * 16 * STRIDE_B;
                #pragma unroll
                for (int kk = 0; kk < 8; kk++) {
                    uint32_t b0, b1, b2, b3;
                    ldsm_x4(b0, b1, b2, b3, ba + kk * 32);
                    mma_bf16(acc[0], A[kk], b0, b1);
                    mma_bf16(acc[1], A[kk], b2, b3);
                }
                const int n0 = nbase + nt * 16;
                #pragma unroll
                for (int c = 0; c < 2; c++) {
                    float2 m = *reinterpret_cast<const float2*>(&m2s[n0 + 8 * c + 2 * tg]);
                    mn[0] = fminf(mn[0], fmaf(-2.0f, acc[c][0], m.x));
                    mn[0] = fminf(mn[0], fmaf(-2.0f, acc[c][1], m.y));
                    mn[1] = fminf(mn[1], fmaf(-2.0f, acc[c][2], m.x));
                    mn[1] = fminf(mn[1], fmaf(-2.0f, acc[c][3], m.y));
                }
            }

            // ---- min across the 4 threads sharing each row ----
            #pragma unroll
            for (int q = 0; q < 2; q++) {
                mn[q] = fminf(mn[q], __shfl_xor_sync(0xffffffffu, mn[q], 1));
                mn[q] = fminf(mn[q], __shfl_xor_sync(0xffffffffu, mn[q], 2));
            }
            if (tg == 0) {
                mhp[(r0 + g)     * 2 + nh] = mn[0];
                mhp[(r0 + g + 8) * 2 + nh] = mn[1];
            }
            BAR_SYNC(5, 512);                                  // consumers only

            // ---- warps 0-7: combine halves for 16 rows, sqrt, sum, atomic ----
            if (wid < 8) {
                const int row = wid * 16 + (lane >> 1);
                const int h   = lane & 1;
                float v = mhp[row * 2 + h];
                v = fminf(v, __shfl_xor_sync(0xffffffffu, v, 1));
                float d = 0.0f;
                if (h == 0) d = sqrtf(fmaxf(z2b[p][row] + v, 0.0f));
                #pragma unroll
                for (int o = 16; o > 0; o >>= 1)
                    d += __shfl_down_sync(0xffffffffu, d, o);
                if (lane == 0) atomicAdd(&g_sum, d);
            }
            BAR_ARRIVE(3 + p, NTHREADS);                       // signal empty
        }
    }

    // ---- finalize: last CTA writes the mean and self-cleans globals ----
    __syncthreads();
    if (tid == 0) {
        __threadfence();
        unsigned int c = atomicAdd(&g_cnt, 1u);
        if (c == (unsigned int)(grid - 1)) {
            out[0] = (*(volatile float*)&g_sum) / (float)L;
            g_sum = 0.0f;
            g_cnt = 0u;
            g_tile = 0u;
        }
    }
}

extern "C" void kernel_launch(void* const* d_in, const int* in_sizes, int n_in,
                              void* d_out, int out_size) {
    const float* z  = (const float*)d_in[0];
    const float* mu = (const float*)d_in[1];
    float* out = (float*)d_out;

    int L = in_sizes[0] / KDIM;   // 65536
    int ntiles = L / MT;          // 512

    static int nsm = 0;
    if (nsm == 0) {
        cudaDeviceGetAttribute(&nsm, cudaDevAttrMultiProcessorCount, 0);
        cudaFuncSetAttribute(km_main, cudaFuncAttributeMaxDynamicSharedMemorySize, SMEM_BYTES);
    }
    int grid = (ntiles < nsm) ? ntiles : nsm;

    km_main<<<grid, NTHREADS, SMEM_BYTES>>>(z, mu, out, L, ntiles, grid);
}

// round 11
// speedup vs baseline: 1.0016x; 1.0016x over previous
#include <cuda_runtime.h>
#include <cuda_fp16.h>
#include <cstdint>
#include <math.h>

// KMeansClusteringLoss via warp-specialized FP16 HMMA pipeline (single kernel).
//   cost(l,c) = |mu_c|^2 - 2 <z_l, mu_c>,  d(l) = sqrt(max(|z_l|^2 + min_c cost, 0))
//   out = mean_l d(l)
//
// R11: fp16 inputs + fp16 accumulators (mma.sync m16n8k16.f16) — f32-accum bf16
// HMMA appears issue-rate-limited on sm_103a; f16-acc runs at full rate.
// z2/m2 computed in fp32 from the SAME fp16-rounded values (exact identity).

#define KDIM  128
#define CDIM  512
#define MT    128
#define NTHREADS 512       // warps 0-7 consumers, 8-15 producers
#define NQ    256          // centroids per consumer warp

#define STRIDE_B 272       // 128 f16 (256B) + 16B pad -> conflict-free LDSM

// dynamic smem layout (bytes)
#define SM_MU    0                          // 512 x 272 = 139264
#define SM_Z0    139264                     // 128 x 272
#define SM_Z1    174080                     // 128 x 272
#define SM_M2    208896                     // 512 f32
#define SM_Z2_0  210944                     // 128 f32
#define SM_Z2_1  211456                     // 128 f32
#define SM_MH0   211968                     // 128 x 2 f32
#define SM_MH1   212992                     // 128 x 2 f32
#define SM_PT    214016                     // 2 ints
#define SMEM_BYTES 214048

__device__ float g_sum;            // zero-init at load; self-cleaned each run
__device__ unsigned int g_cnt;
__device__ unsigned int g_tile;

// ---------------- helpers ----------------
__device__ __forceinline__ uint32_t smem_u32(const void* p) {
    uint32_t a;
    asm("{ .reg .u64 t; cvta.to.shared.u64 t, %1; cvt.u32.u64 %0, t; }" : "=r"(a) : "l"(p));
    return a;
}
__device__ __forceinline__ void ldsm_x4(uint32_t& r0, uint32_t& r1, uint32_t& r2, uint32_t& r3,
                                        uint32_t addr) {
    asm volatile("ldmatrix.sync.aligned.m8n8.x4.shared.b16 {%0,%1,%2,%3}, [%4];"
                 : "=r"(r0), "=r"(r1), "=r"(r2), "=r"(r3) : "r"(addr));
}
// f16 x f16 -> f16 accum. d0 = halves (row g, cols 2tg,2tg+1); d1 = (row g+8).
__device__ __forceinline__ void mma_f16(uint32_t& d0, uint32_t& d1, const uint32_t* a,
                                        uint32_t b0, uint32_t b1) {
    asm volatile(
        "mma.sync.aligned.m16n8k16.row.col.f16.f16.f16.f16 "
        "{%0,%1}, {%2,%3,%4,%5}, {%6,%7}, {%0,%1};"
        : "+r"(d0), "+r"(d1)
        : "r"(a[0]), "r"(a[1]), "r"(a[2]), "r"(a[3]), "r"(b0), "r"(b1));
}
#define BAR_SYNC(id, cnt)   asm volatile("bar.sync %0, %1;"   :: "r"(id), "r"(cnt) : "memory")
#define BAR_ARRIVE(id, cnt) asm volatile("bar.arrive %0, %1;" :: "r"(id), "r"(cnt) : "memory")

// Fill a z tile: global fp32 -> fp16 packed smem.
__device__ __forceinline__ void fill_z(const float* __restrict__ z, int tile,
                                       char* smem, int zoff, int t, int nthr) {
    const size_t m0 = (size_t)tile * MT;
    const int iters = (MT * 16) / nthr;
    #pragma unroll
    for (int it = 0; it < iters; it++) {
        int idx = t + it * nthr;
        int row = idx >> 4, kc = idx & 15;
        const float4* p = reinterpret_cast<const float4*>(z + (m0 + row) * KDIM + kc * 8);
        float4 v0 = p[0], v1 = p[1];
        __half2 h0 = __floats2half2_rn(v0.x, v0.y);
        __half2 h1 = __floats2half2_rn(v0.z, v0.w);
        __half2 h2 = __floats2half2_rn(v1.x, v1.y);
        __half2 h3 = __floats2half2_rn(v1.z, v1.w);
        uint4 q;
        q.x = *reinterpret_cast<uint32_t*>(&h0);
        q.y = *reinterpret_cast<uint32_t*>(&h1);
        q.z = *reinterpret_cast<uint32_t*>(&h2);
        q.w = *reinterpret_cast<uint32_t*>(&h3);
        *reinterpret_cast<uint4*>(smem + zoff + row * STRIDE_B + kc * 16) = q;
    }
}

// |z|^2 second pass (f32 from the f16 values): 256 threads, 2 per row, 1 shfl.
__device__ __forceinline__ void z2_pass(const char* smem, int zoff, float* z2buf, int pt) {
    const int row = pt >> 1;
    const int half = pt & 1;
    float s = 0.0f;
    #pragma unroll
    for (int j = 0; j < 8; j++) {
        uint4 q = *reinterpret_cast<const uint4*>(smem + zoff + row * STRIDE_B
                                                  + half * 128 + j * 16);
        uint32_t u[4] = {q.x, q.y, q.z, q.w};
        #pragma unroll
        for (int e = 0; e < 4; e++) {
            float2 f = __half22float2(*reinterpret_cast<const __half2*>(&u[e]));
            s = fmaf(f.x, f.x, s);
            s = fmaf(f.y, f.y, s);
        }
    }
    s += __shfl_xor_sync(0xffffffffu, s, 1);     // pt parity == lane parity
    if (half == 0) z2buf[row] = s;
}

// ---------------- persistent warp-specialized kernel ----------------
__global__ void __launch_bounds__(NTHREADS, 1) km_main(
    const float* __restrict__ z, const float* __restrict__ mu,
    float* __restrict__ out, int L, int ntiles, int grid)
{
    extern __shared__ char smem[];
    const uint32_t sbase = smem_u32(smem);
    float* m2s = reinterpret_cast<float*>(smem + SM_M2);
    float* z2b[2] = { reinterpret_cast<float*>(smem + SM_Z2_0),
                      reinterpret_cast<float*>(smem + SM_Z2_1) };
    float* mhb[2] = { reinterpret_cast<float*>(smem + SM_MH0),
                      reinterpret_cast<float*>(smem + SM_MH1) };
    int* ptile = reinterpret_cast<int*>(smem + SM_PT);

    const int tid  = threadIdx.x;
    const int wid  = tid >> 5;
    const int lane = tid & 31;

    // ---- prologue: steal tile 0; mu fp32->fp16 into smem; m2 (f32); fill+z2 buf0 ----
    if (tid == 0) ptile[0] = (int)atomicAdd(&g_tile, 1u);

    #pragma unroll
    for (int it = 0; it < 16; it++) {            // 8192 chunks of 16B (f16 out)
        int idx = tid + it * NTHREADS;
        int row = idx >> 4, kc = idx & 15;
        const float4* p = reinterpret_cast<const float4*>(mu + row * KDIM + kc * 8);
        float4 v0 = p[0], v1 = p[1];
        __half2 h0 = __floats2half2_rn(v0.x, v0.y);
        __half2 h1 = __floats2half2_rn(v0.z, v0.w);
        __half2 h2 = __floats2half2_rn(v1.x, v1.y);
        __half2 h3 = __floats2half2_rn(v1.z, v1.w);
        uint4 q;
        q.x = *reinterpret_cast<uint32_t*>(&h0);
        q.y = *reinterpret_cast<uint32_t*>(&h1);
        q.z = *reinterpret_cast<uint32_t*>(&h2);
        q.w = *reinterpret_cast<uint32_t*>(&h3);
        *reinterpret_cast<uint4*>(smem + SM_MU + row * STRIDE_B + kc * 16) = q;
    }
    __syncthreads();

    // m2 per centroid from the f16 values (thread t -> centroid t)
    {
        float s = 0.0f;
        #pragma unroll
        for (int j = 0; j < 16; j++) {
            uint4 q = *reinterpret_cast<const uint4*>(smem + SM_MU + tid * STRIDE_B + j * 16);
            uint32_t u[4] = {q.x, q.y, q.z, q.w};
            #pragma unroll
            for (int e = 0; e < 4; e++) {
                float2 f = __half22float2(*reinterpret_cast<const __half2*>(&u[e]));
                s = fmaf(f.x, f.x, s);
                s = fmaf(f.y, f.y, s);
            }
        }
        m2s[tid] = s;
    }

    fill_z(z, ptile[0], smem, SM_Z0, tid, NTHREADS);
    __syncthreads();
    if (tid < 256) z2_pass(smem, SM_Z0, z2b[0], tid);
    __syncthreads();

    if (wid >= 8) {
        // ================= PRODUCER (warps 8-15) =================
        const int ptid = tid - 256;
        for (int i = 1;; i++) {
            const int p = i & 1;
            if (i >= 2) BAR_SYNC(3 + p, 512);                 // wait buffer empty
            if (ptid == 0) {
                int t = (int)atomicAdd(&g_tile, 1u);
                ptile[p] = (t < ntiles) ? t : -1;
            }
            BAR_SYNC(6, 256);                                  // ptile visible
            const int t = ptile[p];
            if (t >= 0) {
                const int zoff = p ? SM_Z1 : SM_Z0;
                fill_z(z, t, smem, zoff, ptid, 256);
                BAR_SYNC(6, 256);                              // drain STS before z2 reads
                z2_pass(smem, zoff, z2b[p], ptid);
            }
            __threadfence_block();
            BAR_ARRIVE(1 + p, 512);                            // signal full
            if (t < 0) break;
        }
    } else {
        // ================= CONSUMER (warps 0-7) =================
        const int tg   = lane & 3;
        const int g    = lane >> 2;
        const int rw   = wid & 3;           // row-group (m32)
        const int nh   = wid >> 2;          // centroid half (0/1)
        const int r0   = rw * 32;
        const int nbase = nh * NQ;

        const uint32_t bb = sbase + SM_MU
                          + (lane & 7) * STRIDE_B
                          + (((lane >> 3) & 1) ? 16u : 0u)
                          + (lane >> 4) * 8 * STRIDE_B
                          + nbase * STRIDE_B;

        for (int i = 0;; i++) {
            const int p = i & 1;
            if (i >= 1) BAR_SYNC(1 + p, 512);                  // wait buffer full
            const int t = ptile[p];
            if (t < 0) break;
            const uint32_t zb = sbase + (p ? SM_Z1 : SM_Z0);
            float* mhp = mhb[p];

            // ---- A fragments: m32 x K128 register-resident ----
            uint32_t A[2][8][4];
            {
                const uint32_t ab = zb + (lane & 15) * STRIDE_B
                                  + ((lane & 16) ? 16u : 0u) + r0 * STRIDE_B;
                #pragma unroll
                for (int rg = 0; rg < 2; rg++)
                    #pragma unroll
                    for (int kk = 0; kk < 8; kk++)
                        ldsm_x4(A[rg][kk][0], A[rg][kk][1], A[rg][kk][2], A[rg][kk][3],
                                ab + rg * 16 * STRIDE_B + kk * 32);
            }

            // ---- 256 centroids: 16 iters of n16, 4 indep f16-acc chains ----
            float mn[4] = {INFINITY, INFINITY, INFINITY, INFINITY};
            #pragma unroll 1
            for (int nt = 0; nt < NQ / 16; nt++) {
                uint32_t acc[2][2][2];       // [rg][cpair][2 regs], f16x2 each
                #pragma unroll
                for (int rg = 0; rg < 2; rg++)
                    #pragma unroll
                    for (int c = 0; c < 2; c++)
                        acc[rg][c][0] = acc[rg][c][1] = 0u;
                const uint32_t ba = bb + nt * 16 * STRIDE_B;
                #pragma unroll
                for (int kk = 0; kk < 8; kk++) {
                    uint32_t b0, b1, b2, b3;
                    ldsm_x4(b0, b1, b2, b3, ba + kk * 32);
                    mma_f16(acc[0][0][0], acc[0][0][1], A[0][kk], b0, b1);
                    mma_f16(acc[0][1][0], acc[0][1][1], A[0][kk], b2, b3);
                    mma_f16(acc[1][0][0], acc[1][0][1], A[1][kk], b0, b1);
                    mma_f16(acc[1][1][0], acc[1][1][1], A[1][kk], b2, b3);
                }
                const int n0 = nbase + nt * 16;
                #pragma unroll
                for (int c = 0; c < 2; c++) {
                    float2 m = *reinterpret_cast<const float2*>(&m2s[n0 + 8 * c + 2 * tg]);
                    #pragma unroll
                    for (int rg = 0; rg < 2; rg++) {
                        float2 f0 = __half22float2(
                            *reinterpret_cast<const __half2*>(&acc[rg][c][0]));  // row g
                        float2 f1 = __half22float2(
                            *reinterpret_cast<const __half2*>(&acc[rg][c][1]));  // row g+8
                        mn[rg * 2 + 0] = fminf(mn[rg * 2 + 0], fmaf(-2.0f, f0.x, m.x));
                        mn[rg * 2 + 0] = fminf(mn[rg * 2 + 0], fmaf(-2.0f, f0.y, m.y));
                        mn[rg * 2 + 1] = fminf(mn[rg * 2 + 1], fmaf(-2.0f, f1.x, m.x));
                        mn[rg * 2 + 1] = fminf(mn[rg * 2 + 1], fmaf(-2.0f, f1.y, m.y));
                    }
                }
            }

            // ---- min across the 4 threads sharing each row ----
            #pragma unroll
            for (int q = 0; q < 4; q++) {
                mn[q] = fminf(mn[q], __shfl_xor_sync(0xffffffffu, mn[q], 1));
                mn[q] = fminf(mn[q], __shfl_xor_sync(0xffffffffu, mn[q], 2));
            }
            if (tg == 0) {
                mhp[(r0 + g)      * 2 + nh] = mn[0];
                mhp[(r0 + g + 8)  * 2 + nh] = mn[1];
                mhp[(r0 + g + 16) * 2 + nh] = mn[2];
                mhp[(r0 + g + 24) * 2 + nh] = mn[3];
            }
            BAR_SYNC(5, 256);                                  // consumers only

            // ---- per-warp: combine halves for 16 rows, sqrt, sum, atomic ----
            {
                const int row = wid * 16 + (lane >> 1);
                const int h   = lane & 1;
                float v = mhp[row * 2 + h];
                v = fminf(v, __shfl_xor_sync(0xffffffffu, v, 1));
                float d = 0.0f;
                if (h == 0) d = sqrtf(fmaxf(z2b[p][row] + v, 0.0f));
                #pragma unroll
                for (int o = 16; o > 0; o >>= 1)
                    d += __shfl_down_sync(0xffffffffu, d, o);
                if (lane == 0) atomicAdd(&g_sum, d);
            }
            BAR_ARRIVE(3 + p, 512);                            // signal empty
        }
    }

    // ---- finalize: last CTA writes the mean and self-cleans globals ----
    __syncthreads();
    if (tid == 0) {
        __threadfence();
        unsigned int c = atomicAdd(&g_cnt, 1u);
        if (c == (unsigned int)(grid - 1)) {
            out[0] = (*(volatile float*)&g_sum) / (float)L;
            g_sum = 0.0f;
            g_cnt = 0u;
            g_tile = 0u;
        }
    }
}

extern "C" void kernel_launch(void* const* d_in, const int* in_sizes, int n_in,
                              void* d_out, int out_size) {
    const float* z  = (const float*)d_in[0];
    const float* mu = (const float*)d_in[1];
    float* out = (float*)d_out;

    int L = in_sizes[0] / KDIM;   // 65536
    int ntiles = L / MT;          // 512

    static int nsm = 0;
    if (nsm == 0) {
        cudaDeviceGetAttribute(&nsm, cudaDevAttrMultiProcessorCount, 0);
        cudaFuncSetAttribute(km_main, cudaFuncAttributeMaxDynamicSharedMemorySize, SMEM_BYTES);
    }
    int grid = (ntiles < nsm) ? ntiles : nsm;

    km_main<<<grid, NTHREADS, SMEM_BYTES>>>(z, mu, out, L, ntiles, grid);
}